// round 1
// baseline (speedup 1.0000x reference)
#include <cuda_runtime.h>
#include <cuda_bf16.h>
#include <math.h>

// Problem constants
#define BATCH   16384
#define IN_DIM  784
#define NHID    2000
#define KWIN    200
#define NCLS    10

// ---------------- scratch: h = x @ W1^T + b1  (131 MB) ----------------
__device__ float g_h[(size_t)BATCH * NHID];

// ---------------- Kernel A: SGEMM h = x @ W1^T + b1 ----------------
// A: x [BATCH, IN_DIM] row-major. B: W1 [NHID, IN_DIM] row-major (NT gemm).
// 128x128 tile, BK=8, 256 threads, 8x8 per thread.
#define BM 128
#define BN 128
#define BK 8

__global__ __launch_bounds__(256, 2)
void gemm1_kernel(const float* __restrict__ A, const float* __restrict__ W,
                  const float* __restrict__ bias, float* __restrict__ C)
{
    __shared__ __align__(16) float As[BK][BM];
    __shared__ __align__(16) float Bs[BK][BN];

    const int tid = threadIdx.x;
    const int m0 = blockIdx.y * BM;
    const int n0 = blockIdx.x * BN;

    const int tx = tid & 15;        // 0..15 -> n sub-tile
    const int ty = tid >> 4;        // 0..15 -> m sub-tile

    // global load mapping: each thread loads one float4 of A and one of B per tile
    const int l_r = tid >> 1;          // 0..127 row within tile
    const int l_k = (tid & 1) * 4;     // 0 or 4

    const float* Aptr = A + (size_t)(m0 + l_r) * IN_DIM;
    const int bn = n0 + l_r;
    const float* Bptr = W + (size_t)bn * IN_DIM;

    float acc[8][8];
#pragma unroll
    for (int i = 0; i < 8; i++)
#pragma unroll
        for (int j = 0; j < 8; j++) acc[i][j] = 0.f;

    for (int k0 = 0; k0 < IN_DIM; k0 += BK) {
        float4 av = *(const float4*)(Aptr + k0 + l_k);
        float4 bv = make_float4(0.f, 0.f, 0.f, 0.f);
        if (bn < NHID) bv = *(const float4*)(Bptr + k0 + l_k);

        __syncthreads();   // previous iteration's compute must be done
        As[l_k + 0][l_r] = av.x;
        As[l_k + 1][l_r] = av.y;
        As[l_k + 2][l_r] = av.z;
        As[l_k + 3][l_r] = av.w;
        Bs[l_k + 0][l_r] = bv.x;
        Bs[l_k + 1][l_r] = bv.y;
        Bs[l_k + 2][l_r] = bv.z;
        Bs[l_k + 3][l_r] = bv.w;
        __syncthreads();

#pragma unroll
        for (int kk = 0; kk < BK; kk++) {
            float4 a0 = *(const float4*)&As[kk][ty * 8];
            float4 a1 = *(const float4*)&As[kk][ty * 8 + 4];
            float4 b0 = *(const float4*)&Bs[kk][tx * 8];
            float4 b1 = *(const float4*)&Bs[kk][tx * 8 + 4];
            float ra[8] = {a0.x, a0.y, a0.z, a0.w, a1.x, a1.y, a1.z, a1.w};
            float rb[8] = {b0.x, b0.y, b0.z, b0.w, b1.x, b1.y, b1.z, b1.w};
#pragma unroll
            for (int i = 0; i < 8; i++)
#pragma unroll
                for (int j = 0; j < 8; j++)
                    acc[i][j] = fmaf(ra[i], rb[j], acc[i][j]);
        }
    }

    // epilogue: add bias, guarded store (N=2000 not multiple of 128)
#pragma unroll
    for (int i = 0; i < 8; i++) {
        const int m = m0 + ty * 8 + i;
        float* crow = C + (size_t)m * NHID;
#pragma unroll
        for (int j = 0; j < 8; j++) {
            const int n = n0 + tx * 8 + j;
            if (n < NHID) crow[n] = acc[i][j] + bias[n];
        }
    }
}

// ---------------- Kernel B: k-winners + GEMM2 + log_softmax ----------------
// One CTA processes ROWS_PER_CTA rows. W2 + boost staged in smem per CTA.
#define ROWS_PER_CTA 8
#define TB 256

__global__ __launch_bounds__(TB, 2)
void kwin_head_kernel(const float* __restrict__ H,
                      const float* __restrict__ W2,
                      const float* __restrict__ b2,
                      const float* __restrict__ duty,
                      float* __restrict__ out)
{
    extern __shared__ float smem[];
    float*    W2s    = smem;                       // 10*2000
    float*    boosts = W2s + NCLS * NHID;          // 2000
    float*    hs     = boosts + NHID;              // 2000
    unsigned* keys   = (unsigned*)(hs + NHID);     // 2000

    __shared__ unsigned hist[256];
    __shared__ float red[8 * NCLS];
    __shared__ unsigned sPrefix;
    __shared__ int sKRem;

    const int tid = threadIdx.x;
    const int lane = tid & 31;
    const int warp = tid >> 5;

    // stage W2 and boost
    for (int i = tid; i < NCLS * NHID; i += TB) W2s[i] = W2[i];
    for (int i = tid; i < NHID; i += TB)
        boosts[i] = __expf(0.1f - duty[i]);   // boostStrength = 1, target density = 0.1
    __syncthreads();

    for (int r = 0; r < ROWS_PER_CTA; r++) {
        const int row = blockIdx.x * ROWS_PER_CTA + r;
        const float* hrow = H + (size_t)row * NHID;

        // load h, build order-preserving uint keys of boosted h
        for (int i = tid; i < NHID; i += TB) {
            float hv = hrow[i];
            hs[i] = hv;
            float bv = hv * boosts[i];
            unsigned u = __float_as_uint(bv);
            u = (u & 0x80000000u) ? ~u : (u | 0x80000000u);
            keys[i] = u;
        }
        if (tid == 0) { sPrefix = 0u; sKRem = KWIN; }
        __syncthreads();

        // 4-pass MSB radix select: find exact key of the 200th-largest
        for (int shift = 24; shift >= 0; shift -= 8) {
            const unsigned pref = sPrefix;
            const int kRem = sKRem;
            hist[tid] = 0u;
            __syncthreads();
            const unsigned hiMask = (shift == 24) ? 0u : (0xFFFFFFFFu << (shift + 8));
            for (int i = tid; i < NHID; i += TB) {
                unsigned u = keys[i];
                if ((u & hiMask) == pref)
                    atomicAdd(&hist[(u >> shift) & 255u], 1u);
            }
            __syncthreads();
            // suffix sum for my bin: mySuf = sum hist[tid..255]
            unsigned mySuf = 0u;
            for (int b = 255; b >= tid; b--) mySuf += hist[b];
            const unsigned below = mySuf - hist[tid]; // suffix(tid+1)
            if ((int)mySuf >= kRem && (int)below < kRem) {   // exactly one thread
                sPrefix = pref | ((unsigned)tid << shift);
                sKRem = kRem - (int)below;
            }
            __syncthreads();
        }
        const unsigned T = sPrefix;     // exact key of 200th-largest boosted value
        const int needEq = sKRem;       // how many key==T entries win (lowest index first)

        // accumulate logits over winners (keep ORIGINAL h values)
        float acc[NCLS];
#pragma unroll
        for (int c = 0; c < NCLS; c++) acc[c] = 0.f;

        for (int i = tid; i < NHID; i += TB) {
            const unsigned u = keys[i];
            bool win = (u > T);
            if (!win && u == T) {
                int rank = 0;
                for (int j = 0; j < i; j++) rank += (keys[j] == T);
                win = (rank < needEq);
            }
            if (win) {
                const float hv = hs[i];
#pragma unroll
                for (int c = 0; c < NCLS; c++)
                    acc[c] = fmaf(hv, W2s[c * NHID + i], acc[c]);
            }
        }

        // deterministic reduction: warp shuffle then cross-warp by thread 0
#pragma unroll
        for (int off = 16; off; off >>= 1)
#pragma unroll
            for (int c = 0; c < NCLS; c++)
                acc[c] += __shfl_xor_sync(0xFFFFFFFFu, acc[c], off);
        if (lane == 0)
#pragma unroll
            for (int c = 0; c < NCLS; c++) red[warp * NCLS + c] = acc[c];
        __syncthreads();

        if (tid == 0) {
            float lg[NCLS];
#pragma unroll
            for (int c = 0; c < NCLS; c++) {
                float s = b2[c];
#pragma unroll
                for (int w = 0; w < 8; w++) s += red[w * NCLS + c];
                lg[c] = s;
            }
            float mx = lg[0];
#pragma unroll
            for (int c = 1; c < NCLS; c++) mx = fmaxf(mx, lg[c]);
            float se = 0.f;
#pragma unroll
            for (int c = 0; c < NCLS; c++) se += expf(lg[c] - mx);
            const float lse = mx + logf(se);
            float* orow = out + (size_t)row * NCLS;
#pragma unroll
            for (int c = 0; c < NCLS; c++) orow[c] = lg[c] - lse;
        }
        __syncthreads();   // before hs/keys are overwritten for next row
    }
}

// ---------------- launch ----------------
extern "C" void kernel_launch(void* const* d_in, const int* in_sizes, int n_in,
                              void* d_out, int out_size)
{
    const float* x    = (const float*)d_in[0];   // [16384, 784]
    const float* W1   = (const float*)d_in[1];   // [2000, 784]
    const float* b1   = (const float*)d_in[2];   // [2000]
    const float* W2   = (const float*)d_in[3];   // [10, 2000]
    const float* b2   = (const float*)d_in[4];   // [10]
    const float* duty = (const float*)d_in[5];   // [2000]
    float* out = (float*)d_out;                  // [16384, 10]

    float* h;
    cudaGetSymbolAddress((void**)&h, g_h);

    // GEMM1: h = x @ W1^T + b1
    dim3 gridA((NHID + BN - 1) / BN, BATCH / BM);
    gemm1_kernel<<<gridA, 256>>>(x, W1, b1, h);

    // k-winners + head + log_softmax
    const size_t smemB = (size_t)(NCLS * NHID + NHID + NHID) * sizeof(float)
                       + (size_t)NHID * sizeof(unsigned);     // 104000 B
    cudaFuncSetAttribute(kwin_head_kernel,
                         cudaFuncAttributeMaxDynamicSharedMemorySize, (int)smemB);
    kwin_head_kernel<<<BATCH / ROWS_PER_CTA, TB, smemB>>>(h, W2, b2, duty, out);
}

// round 3
// speedup vs baseline: 2.7642x; 2.7642x over previous
#include <cuda_runtime.h>
#include <cuda_bf16.h>
#include <cstdint>
#include <math.h>

// Problem constants
#define BATCH   16384
#define IN_DIM  784
#define NHID    2000
#define KWIN    200
#define NCLS    10

// ---------------- device scratch ----------------
__device__ __align__(256) float         g_h  [(size_t)BATCH * NHID];
__device__ __align__(256) __nv_bfloat16 g_xhi[(size_t)BATCH * IN_DIM];
__device__ __align__(256) __nv_bfloat16 g_xlo[(size_t)BATCH * IN_DIM];
__device__ __align__(256) __nv_bfloat16 g_whi[(size_t)NHID * IN_DIM];
__device__ __align__(256) __nv_bfloat16 g_wlo[(size_t)NHID * IN_DIM];

// ---------------- helpers ----------------
__device__ __forceinline__ uint32_t smem_u32(const void* p) {
    uint32_t a;
    asm("{ .reg .u64 t; cvta.to.shared.u64 t, %1; cvt.u32.u64 %0, t; }" : "=r"(a) : "l"(p));
    return a;
}

__device__ __forceinline__ void cpa16z(uint32_t dst, const void* src, bool valid) {
    int sz = valid ? 16 : 0;
    asm volatile("cp.async.cg.shared.global [%0], [%1], 16, %2;"
                 :: "r"(dst), "l"(src), "r"(sz));
}

__device__ __forceinline__ void ldsm_x4(uint32_t addr, uint32_t* r) {
    asm volatile("ldmatrix.sync.aligned.m8n8.x4.shared.b16 {%0,%1,%2,%3}, [%4];"
                 : "=r"(r[0]), "=r"(r[1]), "=r"(r[2]), "=r"(r[3]) : "r"(addr));
}

__device__ __forceinline__ void mma_bf16(float* c, const uint32_t* a, uint32_t b0, uint32_t b1) {
    asm volatile("mma.sync.aligned.m16n8k16.row.col.f32.bf16.bf16.f32 "
                 "{%0,%1,%2,%3}, {%4,%5,%6,%7}, {%8,%9}, {%0,%1,%2,%3};"
                 : "+f"(c[0]), "+f"(c[1]), "+f"(c[2]), "+f"(c[3])
                 : "r"(a[0]), "r"(a[1]), "r"(a[2]), "r"(a[3]), "r"(b0), "r"(b1));
}

// ---------------- split fp32 -> (bf16 hi, bf16 lo) ----------------
__global__ void split_kernel(const float* __restrict__ src,
                             __nv_bfloat16* __restrict__ hi,
                             __nv_bfloat16* __restrict__ lo, int n4)
{
    int i = blockIdx.x * blockDim.x + threadIdx.x;
    const int stride = gridDim.x * blockDim.x;
    for (; i < n4; i += stride) {
        float4 v = ((const float4*)src)[i];
        __nv_bfloat16 h0 = __float2bfloat16(v.x);
        __nv_bfloat16 h1 = __float2bfloat16(v.y);
        __nv_bfloat16 h2 = __float2bfloat16(v.z);
        __nv_bfloat16 h3 = __float2bfloat16(v.w);
        __nv_bfloat162 ha; ha.x = h0; ha.y = h1;
        __nv_bfloat162 hb; hb.x = h2; hb.y = h3;
        ((__nv_bfloat162*)hi)[2 * i]     = ha;
        ((__nv_bfloat162*)hi)[2 * i + 1] = hb;
        __nv_bfloat162 la, lb;
        la.x = __float2bfloat16(v.x - __bfloat162float(h0));
        la.y = __float2bfloat16(v.y - __bfloat162float(h1));
        lb.x = __float2bfloat16(v.z - __bfloat162float(h2));
        lb.y = __float2bfloat16(v.w - __bfloat162float(h3));
        ((__nv_bfloat162*)lo)[2 * i]     = la;
        ((__nv_bfloat162*)lo)[2 * i + 1] = lb;
    }
}

// ---------------- HMMA GEMM1: h = x @ W1^T + b1 (split-bf16, 3 terms) ----------------
// CTA tile 128x128, BK=32, 256 threads (8 warps), warp tile 64x32.
// Smem per stage: 4 matrices (Ahi, Alo, Bhi, Blo), 128 rows x 32 bf16, row stride 80B.
#define BM 128
#define BN 128
#define BKG 32
#define NCHUNK 25              // ceil(784/32); last chunk half zero-filled
#define ROW_STRIDE 80          // 64B data + 16B pad (conflict-free ldmatrix)
#define MAT_SZ (128 * ROW_STRIDE)   // 10240 B
#define STAGE_SZ (4 * MAT_SZ)       // 40960 B
#define SMEM_GEMM (2 * STAGE_SZ)    // 81920 B

__global__ __launch_bounds__(256)
void gemm1_mma(const __nv_bfloat16* __restrict__ xhi, const __nv_bfloat16* __restrict__ xlo,
               const __nv_bfloat16* __restrict__ whi, const __nv_bfloat16* __restrict__ wlo,
               const float* __restrict__ bias, float* __restrict__ H)
{
    extern __shared__ __align__(1024) char smem[];
    const uint32_t sb = smem_u32(smem);
    const int tid = threadIdx.x;
    const int lane = tid & 31;
    const int wid = tid >> 5;
    const int wm = wid & 1;        // 0..1 : m sub-tile (64 rows)
    const int wn = wid >> 1;       // 0..3 : n sub-tile (32 cols)
    const int m0 = blockIdx.y * BM;
    const int n0 = blockIdx.x * BN;

    // ---- async tile loader: 2048 cp.async of 16B per chunk ----
    auto load_chunk = [&](int c, int s) {
        const int k0 = c * BKG;
        const uint32_t base = sb + s * STAGE_SZ;
        #pragma unroll
        for (int it = tid; it < 2048; it += 256) {
            const int mat = it >> 9;          // 0:Ahi 1:Alo 2:Bhi 3:Blo
            const int idx = it & 511;
            const int row = idx >> 2;
            const int seg = idx & 3;
            const int k = k0 + seg * 8;
            bool valid = (k < IN_DIM);
            const __nv_bfloat16* src;
            if (mat < 2) {
                src = (mat == 0 ? xhi : xlo) + (size_t)(m0 + row) * IN_DIM + k;
            } else {
                const int n = n0 + row;
                valid = valid && (n < NHID);
                const int nn = (n < NHID) ? n : 0;
                src = (mat == 2 ? whi : wlo) + (size_t)nn * IN_DIM + k;
            }
            cpa16z(base + mat * MAT_SZ + row * ROW_STRIDE + seg * 16, src, valid);
        }
        asm volatile("cp.async.commit_group;");
    };

    float acc[4][4][4];
    #pragma unroll
    for (int i = 0; i < 4; i++)
        #pragma unroll
        for (int j = 0; j < 4; j++)
            #pragma unroll
            for (int q = 0; q < 4; q++) acc[i][j][q] = 0.f;

    // lane-dependent ldmatrix offsets (byte offsets within a matrix)
    const uint32_t aRowOff = (uint32_t)((lane & 15) * ROW_STRIDE + (lane >> 4) * 16);
    const uint32_t bRowOff = (uint32_t)((((lane >> 4) * 8) + (lane & 7)) * ROW_STRIDE
                                        + (((lane >> 3) & 1) * 16));

    load_chunk(0, 0);

    for (int c = 0; c < NCHUNK; c++) {
        const int s = c & 1;
        if (c + 1 < NCHUNK) {
            load_chunk(c + 1, s ^ 1);
            asm volatile("cp.async.wait_group 1;");
        } else {
            asm volatile("cp.async.wait_group 0;");
        }
        __syncthreads();

        const uint32_t base = sb + s * STAGE_SZ;
        #pragma unroll
        for (int kk = 0; kk < 2; kk++) {          // two k16 steps per chunk
            const uint32_t kOff = kk * 32;        // 16 bf16 = 32 bytes

            uint32_t ra[2][4][4];                 // [hi/lo][m-tile][reg]
            #pragma unroll
            for (int i = 0; i < 4; i++) {
                const uint32_t ao = base + (wm * 64 + i * 16) * ROW_STRIDE + aRowOff + kOff;
                ldsm_x4(ao,          ra[0][i]);
                ldsm_x4(ao + MAT_SZ, ra[1][i]);
            }
            uint32_t rb[2][2][4];                 // [hi/lo][n16-group][reg]
            #pragma unroll
            for (int jj = 0; jj < 2; jj++) {
                const uint32_t bo = base + 2 * MAT_SZ + (wn * 32 + jj * 16) * ROW_STRIDE
                                  + bRowOff + kOff;
                ldsm_x4(bo,          rb[0][jj]);
                ldsm_x4(bo + MAT_SZ, rb[1][jj]);
            }

            #pragma unroll
            for (int i = 0; i < 4; i++) {
                #pragma unroll
                for (int j = 0; j < 4; j++) {
                    const int jj = j >> 1;
                    const int pr = (j & 1) * 2;
                    mma_bf16(acc[i][j], ra[0][i], rb[0][jj][pr], rb[0][jj][pr + 1]); // hi*hi
                    mma_bf16(acc[i][j], ra[0][i], rb[1][jj][pr], rb[1][jj][pr + 1]); // hi*lo
                    mma_bf16(acc[i][j], ra[1][i], rb[0][jj][pr], rb[0][jj][pr + 1]); // lo*hi
                }
            }
        }
        __syncthreads();   // all warps done reading stage s before it is reloaded
    }

    // ---- epilogue: bias + store (fp32) ----
    #pragma unroll
    for (int i = 0; i < 4; i++) {
        const int r0 = m0 + wm * 64 + i * 16 + (lane >> 2);
        #pragma unroll
        for (int j = 0; j < 4; j++) {
            const int col = n0 + wn * 32 + j * 8 + (lane & 3) * 2;
            if (col < NHID) {
                const float bx = __ldg(bias + col);
                const float by = __ldg(bias + col + 1);
                float2 v0 = make_float2(acc[i][j][0] + bx, acc[i][j][1] + by);
                float2 v1 = make_float2(acc[i][j][2] + bx, acc[i][j][3] + by);
                *(float2*)(H + (size_t)r0 * NHID + col)       = v0;
                *(float2*)(H + (size_t)(r0 + 8) * NHID + col) = v1;
            }
        }
    }
}

// ---------------- Kernel B: k-winners + GEMM2 + log_softmax ----------------
#define TBB 256
#define ROWS_B 2

__global__ __launch_bounds__(TBB, 4)
void kwin_head_kernel(const float* __restrict__ H,
                      const float* __restrict__ W2,
                      const float* __restrict__ b2,
                      const float* __restrict__ duty,
                      float* __restrict__ out)
{
    __shared__ float    boosts[NHID];
    __shared__ float    hs[NHID];
    __shared__ unsigned keys[NHID];
    __shared__ unsigned hist[256];
    __shared__ unsigned wsum[8];
    __shared__ float    red[8 * NCLS];
    __shared__ unsigned sPrefix;
    __shared__ int      sKRem;

    const int tid = threadIdx.x;
    const int lane = tid & 31;
    const int warp = tid >> 5;

    for (int i = tid; i < NHID; i += TBB)
        boosts[i] = __expf(0.1f - duty[i]);   // boostStrength=1, targetDensity=k/n=0.1
    __syncthreads();

    for (int r = 0; r < ROWS_B; r++) {
        const int row = blockIdx.x * ROWS_B + r;
        const float* hrow = H + (size_t)row * NHID;

        for (int i = tid; i < NHID; i += TBB) {
            const float hv = hrow[i];
            hs[i] = hv;
            unsigned u = __float_as_uint(hv * boosts[i]);
            u = (u & 0x80000000u) ? ~u : (u | 0x80000000u);
            keys[i] = u;
        }
        if (tid == 0) { sPrefix = 0u; sKRem = KWIN; }
        __syncthreads();

        // 4-pass MSB radix select: exact key of the 200th-largest boosted value
        for (int shift = 24; shift >= 0; shift -= 8) {
            const unsigned pref = sPrefix;
            const int kRem = sKRem;
            hist[tid] = 0u;
            __syncthreads();
            const unsigned hiMask = (shift == 24) ? 0u : (0xFFFFFFFFu << (shift + 8));
            for (int i = tid; i < NHID; i += TBB) {
                const unsigned u = keys[i];
                if ((u & hiMask) == pref)
                    atomicAdd(&hist[(u >> shift) & 255u], 1u);
            }
            __syncthreads();
            // suffix sum via warp scan over reversed bins
            const unsigned bin = 255u - (unsigned)tid;
            const unsigned cnt = hist[bin];
            unsigned v = cnt;
#pragma unroll
            for (int off = 1; off < 32; off <<= 1) {
                const unsigned t = __shfl_up_sync(0xFFFFFFFFu, v, off);
                if (lane >= off) v += t;
            }
            if (lane == 31) wsum[warp] = v;
            __syncthreads();
            if (tid == 0) {
                unsigned s = 0;
                for (int w = 0; w < 8; w++) { const unsigned t = wsum[w]; wsum[w] = s; s += t; }
            }
            __syncthreads();
            const unsigned suf = v + wsum[warp];     // sum hist[bin..255]
            const unsigned below = suf - cnt;
            if ((int)suf >= kRem && (int)below < kRem) {
                sPrefix = pref | (bin << shift);
                sKRem = kRem - (int)below;
            }
            __syncthreads();
        }
        const unsigned T = sPrefix;
        const int needEq = sKRem;   // ties at T win by ascending index

        float acc[NCLS];
#pragma unroll
        for (int c = 0; c < NCLS; c++) acc[c] = 0.f;

        for (int i = tid; i < NHID; i += TBB) {
            const unsigned u = keys[i];
            bool win = (u > T);
            if (!win && u == T) {
                int rank = 0;
                for (int j = 0; j < i; j++) rank += (keys[j] == T);
                win = (rank < needEq);
            }
            if (win) {
                const float hv = hs[i];
#pragma unroll
                for (int c = 0; c < NCLS; c++)
                    acc[c] = fmaf(hv, __ldg(&W2[c * NHID + i]), acc[c]);
            }
        }

#pragma unroll
        for (int off = 16; off; off >>= 1)
#pragma unroll
            for (int c = 0; c < NCLS; c++)
                acc[c] += __shfl_xor_sync(0xFFFFFFFFu, acc[c], off);
        if (lane == 0)
#pragma unroll
            for (int c = 0; c < NCLS; c++) red[warp * NCLS + c] = acc[c];
        __syncthreads();

        if (tid == 0) {
            float lg[NCLS];
#pragma unroll
            for (int c = 0; c < NCLS; c++) {
                float s = b2[c];
#pragma unroll
                for (int w = 0; w < 8; w++) s += red[w * NCLS + c];
                lg[c] = s;
            }
            float mx = lg[0];
#pragma unroll
            for (int c = 1; c < NCLS; c++) mx = fmaxf(mx, lg[c]);
            float se = 0.f;
#pragma unroll
            for (int c = 0; c < NCLS; c++) se += expf(lg[c] - mx);
            const float lse = mx + logf(se);
            float* orow = out + (size_t)row * NCLS;
#pragma unroll
            for (int c = 0; c < NCLS; c++) orow[c] = lg[c] - lse;
        }
        __syncthreads();
    }
}

// ---------------- launch ----------------
extern "C" void kernel_launch(void* const* d_in, const int* in_sizes, int n_in,
                              void* d_out, int out_size)
{
    const float* x    = (const float*)d_in[0];   // [16384, 784]
    const float* W1   = (const float*)d_in[1];   // [2000, 784]
    const float* b1   = (const float*)d_in[2];   // [2000]
    const float* W2   = (const float*)d_in[3];   // [10, 2000]
    const float* b2   = (const float*)d_in[4];   // [10]
    const float* duty = (const float*)d_in[5];   // [2000]
    float* out = (float*)d_out;                  // [16384, 10]

    float* h;            cudaGetSymbolAddress((void**)&h,   g_h);
    __nv_bfloat16* xhi;  cudaGetSymbolAddress((void**)&xhi, g_xhi);
    __nv_bfloat16* xlo;  cudaGetSymbolAddress((void**)&xlo, g_xlo);
    __nv_bfloat16* whi;  cudaGetSymbolAddress((void**)&whi, g_whi);
    __nv_bfloat16* wlo;  cudaGetSymbolAddress((void**)&wlo, g_wlo);

    split_kernel<<<1024, 256>>>(x,  xhi, xlo, (BATCH * IN_DIM) / 4);
    split_kernel<<<512,  256>>>(W1, whi, wlo, (NHID  * IN_DIM) / 4);

    cudaFuncSetAttribute(gemm1_mma, cudaFuncAttributeMaxDynamicSharedMemorySize, SMEM_GEMM);
    dim3 gridG((NHID + BN - 1) / BN, BATCH / BM);   // (16, 128)
    gemm1_mma<<<gridG, 256, SMEM_GEMM>>>(xhi, xlo, whi, wlo, b1, h);

    kwin_head_kernel<<<BATCH / ROWS_B, TBB>>>(h, W2, b2, duty, out);
}

// round 4
// speedup vs baseline: 3.7994x; 1.3745x over previous
#include <cuda_runtime.h>
#include <cuda_fp16.h>
#include <cstdint>
#include <math.h>

// Problem constants
#define BATCH   16384
#define IN_DIM  784
#define NHID    2000
#define KWIN    200
#define NCLS    10

// ---------------- device scratch ----------------
__device__ __align__(256) float  g_h  [(size_t)BATCH * NHID];
__device__ __align__(256) __half g_xhi[(size_t)BATCH * IN_DIM];
__device__ __align__(256) __half g_xlo[(size_t)BATCH * IN_DIM];
__device__ __align__(256) __half g_whi[(size_t)NHID * IN_DIM];
__device__ __align__(256) __half g_wlo[(size_t)NHID * IN_DIM];

// ---------------- helpers ----------------
__device__ __forceinline__ uint32_t smem_u32(const void* p) {
    uint32_t a;
    asm("{ .reg .u64 t; cvta.to.shared.u64 t, %1; cvt.u32.u64 %0, t; }" : "=r"(a) : "l"(p));
    return a;
}

__device__ __forceinline__ void cpa16z(uint32_t dst, const void* src, bool valid) {
    int sz = valid ? 16 : 0;
    asm volatile("cp.async.cg.shared.global [%0], [%1], 16, %2;"
                 :: "r"(dst), "l"(src), "r"(sz));
}

__device__ __forceinline__ void ldsm_x4(uint32_t addr, uint32_t* r) {
    asm volatile("ldmatrix.sync.aligned.m8n8.x4.shared.b16 {%0,%1,%2,%3}, [%4];"
                 : "=r"(r[0]), "=r"(r[1]), "=r"(r[2]), "=r"(r[3]) : "r"(addr));
}

__device__ __forceinline__ void mma_f16(float* c, const uint32_t* a, uint32_t b0, uint32_t b1) {
    asm volatile("mma.sync.aligned.m16n8k16.row.col.f32.f16.f16.f32 "
                 "{%0,%1,%2,%3}, {%4,%5,%6,%7}, {%8,%9}, {%0,%1,%2,%3};"
                 : "+f"(c[0]), "+f"(c[1]), "+f"(c[2]), "+f"(c[3])
                 : "r"(a[0]), "r"(a[1]), "r"(a[2]), "r"(a[3]), "r"(b0), "r"(b1));
}

// ---------------- split fp32 -> (fp16 hi, fp16 lo-residual) ----------------
__global__ void split_kernel(const float* __restrict__ src,
                             __half* __restrict__ hi,
                             __half* __restrict__ lo, int n4)
{
    int i = blockIdx.x * blockDim.x + threadIdx.x;
    const int stride = gridDim.x * blockDim.x;
    for (; i < n4; i += stride) {
        float4 v = ((const float4*)src)[i];
        __half h0 = __float2half_rn(v.x);
        __half h1 = __float2half_rn(v.y);
        __half h2 = __float2half_rn(v.z);
        __half h3 = __float2half_rn(v.w);
        __half2 ha; ha.x = h0; ha.y = h1;
        __half2 hb; hb.x = h2; hb.y = h3;
        ((__half2*)hi)[2 * i]     = ha;
        ((__half2*)hi)[2 * i + 1] = hb;
        __half2 la, lb;
        la.x = __float2half_rn(v.x - __half2float(h0));
        la.y = __float2half_rn(v.y - __half2float(h1));
        lb.x = __float2half_rn(v.z - __half2float(h2));
        lb.y = __float2half_rn(v.w - __half2float(h3));
        ((__half2*)lo)[2 * i]     = la;
        ((__half2*)lo)[2 * i + 1] = lb;
    }
}

// ---------------- HMMA GEMM1: h = x @ W1^T + b1 (split-fp16, 3 terms, 1 acc) ----------------
#define BM 128
#define BN 128
#define BKG 32
#define NCHUNK 25              // ceil(784/32); last chunk half zero-filled
#define ROW_STRIDE 80          // 64B data + 16B pad (conflict-free ldmatrix)
#define MAT_SZ (128 * ROW_STRIDE)   // 10240 B
#define STAGE_SZ (4 * MAT_SZ)       // 40960 B
#define SMEM_GEMM (2 * STAGE_SZ)    // 81920 B

__global__ __launch_bounds__(256)
void gemm1_mma(const __half* __restrict__ xhi, const __half* __restrict__ xlo,
               const __half* __restrict__ whi, const __half* __restrict__ wlo,
               const float* __restrict__ bias, float* __restrict__ H)
{
    extern __shared__ __align__(1024) char smem[];
    const uint32_t sb = smem_u32(smem);
    const int tid = threadIdx.x;
    const int lane = tid & 31;
    const int wid = tid >> 5;
    const int wm = wid & 1;        // 0..1 : m sub-tile (64 rows)
    const int wn = wid >> 1;       // 0..3 : n sub-tile (32 cols)
    const int m0 = blockIdx.y * BM;
    const int n0 = blockIdx.x * BN;

    auto load_chunk = [&](int c, int s) {
        const int k0 = c * BKG;
        const uint32_t base = sb + s * STAGE_SZ;
        #pragma unroll
        for (int it = tid; it < 2048; it += 256) {
            const int mat = it >> 9;          // 0:Ahi 1:Alo 2:Bhi 3:Blo
            const int idx = it & 511;
            const int row = idx >> 2;
            const int seg = idx & 3;
            const int k = k0 + seg * 8;
            bool valid = (k < IN_DIM);
            const __half* src;
            if (mat < 2) {
                src = (mat == 0 ? xhi : xlo) + (size_t)(m0 + row) * IN_DIM + k;
            } else {
                const int n = n0 + row;
                valid = valid && (n < NHID);
                const int nn = (n < NHID) ? n : 0;
                src = (mat == 2 ? whi : wlo) + (size_t)nn * IN_DIM + k;
            }
            cpa16z(base + mat * MAT_SZ + row * ROW_STRIDE + seg * 16, src, valid);
        }
        asm volatile("cp.async.commit_group;");
    };

    float acc[4][4][4];
    #pragma unroll
    for (int i = 0; i < 4; i++)
        #pragma unroll
        for (int j = 0; j < 4; j++)
            #pragma unroll
            for (int q = 0; q < 4; q++) acc[i][j][q] = 0.f;

    const uint32_t aRowOff = (uint32_t)((lane & 15) * ROW_STRIDE + (lane >> 4) * 16);
    const uint32_t bRowOff = (uint32_t)((((lane >> 4) * 8) + (lane & 7)) * ROW_STRIDE
                                        + (((lane >> 3) & 1) * 16));

    load_chunk(0, 0);

    for (int c = 0; c < NCHUNK; c++) {
        const int s = c & 1;
        if (c + 1 < NCHUNK) {
            load_chunk(c + 1, s ^ 1);
            asm volatile("cp.async.wait_group 1;");
        } else {
            asm volatile("cp.async.wait_group 0;");
        }
        __syncthreads();

        const uint32_t base = sb + s * STAGE_SZ;
        #pragma unroll
        for (int kk = 0; kk < 2; kk++) {          // two k16 steps per chunk
            const uint32_t kOff = kk * 32;

            uint32_t ra[2][4][4];                 // [hi/lo][m-tile][reg]
            #pragma unroll
            for (int i = 0; i < 4; i++) {
                const uint32_t ao = base + (wm * 64 + i * 16) * ROW_STRIDE + aRowOff + kOff;
                ldsm_x4(ao,          ra[0][i]);
                ldsm_x4(ao + MAT_SZ, ra[1][i]);
            }
            uint32_t rb[2][2][4];                 // [hi/lo][n16-group][reg]
            #pragma unroll
            for (int jj = 0; jj < 2; jj++) {
                const uint32_t bo = base + 2 * MAT_SZ + (wn * 32 + jj * 16) * ROW_STRIDE
                                  + bRowOff + kOff;
                ldsm_x4(bo,          rb[0][jj]);
                ldsm_x4(bo + MAT_SZ, rb[1][jj]);
            }

            #pragma unroll
            for (int i = 0; i < 4; i++) {
                #pragma unroll
                for (int j = 0; j < 4; j++) {
                    const int jj = j >> 1;
                    const int pr = (j & 1) * 2;
                    mma_f16(acc[i][j], ra[0][i], rb[0][jj][pr], rb[0][jj][pr + 1]); // hi*hi
                    mma_f16(acc[i][j], ra[0][i], rb[1][jj][pr], rb[1][jj][pr + 1]); // hi*lo
                    mma_f16(acc[i][j], ra[1][i], rb[0][jj][pr], rb[0][jj][pr + 1]); // lo*hi
                }
            }
        }
        __syncthreads();
    }

    #pragma unroll
    for (int i = 0; i < 4; i++) {
        const int r0 = m0 + wm * 64 + i * 16 + (lane >> 2);
        #pragma unroll
        for (int j = 0; j < 4; j++) {
            const int col = n0 + wn * 32 + j * 8 + (lane & 3) * 2;
            if (col < NHID) {
                const float bx = __ldg(bias + col);
                const float by = __ldg(bias + col + 1);
                float2 v0 = make_float2(acc[i][j][0] + bx, acc[i][j][1] + by);
                float2 v1 = make_float2(acc[i][j][2] + bx, acc[i][j][3] + by);
                *(float2*)(H + (size_t)r0 * NHID + col)       = v0;
                *(float2*)(H + (size_t)(r0 + 8) * NHID + col) = v1;
            }
        }
    }
}

// ---------------- Kernel B: k-winners + GEMM2 + log_softmax ----------------
// 2-pass radix (top-8 bits, bits 16-23) + boundary-bin candidate compaction.
#define TBB 256
#define ROWS_B 2
#define MAXCAND 256

__global__ __launch_bounds__(TBB)
void kwin_head_kernel(const float* __restrict__ H,
                      const float* __restrict__ W2,
                      const float* __restrict__ b2,
                      const float* __restrict__ duty,
                      float* __restrict__ out)
{
    __shared__ __align__(16) float    hs[NHID];
    __shared__ __align__(16) float    boosts[NHID];
    __shared__ unsigned keys[NHID];
    __shared__ unsigned hist[256];
    __shared__ unsigned wsum[8];
    __shared__ float    red[8 * NCLS];
    __shared__ unsigned sB1, sThr16;
    __shared__ int      sK1, sK2;
    __shared__ unsigned candCnt, winCnt;
    __shared__ unsigned candKey[MAXCAND];
    __shared__ int      candIdx[MAXCAND];
    __shared__ int      winList[MAXCAND];

    const int tid = threadIdx.x;
    const int lane = tid & 31;
    const int warp = tid >> 5;

    for (int i = tid; i < NHID; i += TBB)
        boosts[i] = expf(0.1f - duty[i]);   // boostStrength=1, targetDensity=k/n=0.1
    __syncthreads();

    for (int r = 0; r < ROWS_B; r++) {
        const int row = blockIdx.x * ROWS_B + r;
        const float* hrow = H + (size_t)row * NHID;

        hist[tid] = 0u;
        if (tid == 0) { candCnt = 0u; winCnt = 0u; }
        __syncthreads();

        // phase 1: float4 load + key build + top-byte histogram
        for (int v = tid; v < NHID / 4; v += TBB) {
            const float4 hv = ((const float4*)hrow)[v];
            const float4 bv = ((const float4*)boosts)[v];
            ((float4*)hs)[v] = hv;
            const int i = v * 4;
            float hb[4] = {hv.x * bv.x, hv.y * bv.y, hv.z * bv.z, hv.w * bv.w};
            #pragma unroll
            for (int q = 0; q < 4; q++) {
                unsigned u = __float_as_uint(hb[q]);
                u = (u & 0x80000000u) ? ~u : (u | 0x80000000u);
                keys[i + q] = u;
                atomicAdd(&hist[u >> 24], 1u);
            }
        }
        __syncthreads();

        // scan 1: suffix sums over 256 bins, kRem = KWIN
        {
            const unsigned bin = 255u - (unsigned)tid;
            const unsigned cnt = hist[bin];
            unsigned v = cnt;
            #pragma unroll
            for (int off = 1; off < 32; off <<= 1) {
                const unsigned t = __shfl_up_sync(0xFFFFFFFFu, v, off);
                if (lane >= off) v += t;
            }
            if (lane == 31) wsum[warp] = v;
            __syncthreads();
            if (tid == 0) {
                unsigned s = 0;
                for (int w = 0; w < 8; w++) { const unsigned t = wsum[w]; wsum[w] = s; s += t; }
            }
            __syncthreads();
            const unsigned suf = v + wsum[warp];
            const unsigned below = suf - cnt;
            if ((int)suf >= KWIN && (int)below < KWIN) {
                sB1 = bin;
                sK1 = KWIN - (int)below;
            }
        }
        __syncthreads();
        const unsigned b1 = sB1;
        const int k1 = sK1;

        // phase 2: histogram of bits 16..23 among top-byte == b1
        hist[tid] = 0u;
        __syncthreads();
        for (int i = tid; i < NHID; i += TBB) {
            const unsigned u = keys[i];
            if ((u >> 24) == b1) atomicAdd(&hist[(u >> 16) & 255u], 1u);
        }
        __syncthreads();

        // scan 2
        {
            const unsigned bin = 255u - (unsigned)tid;
            const unsigned cnt = hist[bin];
            unsigned v = cnt;
            #pragma unroll
            for (int off = 1; off < 32; off <<= 1) {
                const unsigned t = __shfl_up_sync(0xFFFFFFFFu, v, off);
                if (lane >= off) v += t;
            }
            if (lane == 31) wsum[warp] = v;
            __syncthreads();
            if (tid == 0) {
                unsigned s = 0;
                for (int w = 0; w < 8; w++) { const unsigned t = wsum[w]; wsum[w] = s; s += t; }
            }
            __syncthreads();
            const unsigned suf = v + wsum[warp];
            const unsigned below = suf - cnt;
            if ((int)suf >= k1 && (int)below < k1) {
                sThr16 = (b1 << 8) | bin;
                sK2 = k1 - (int)below;
            }
        }
        __syncthreads();
        const unsigned thr16 = sThr16;
        const int k2 = sK2;

        // phase 3: compact boundary-bin candidates
        for (int i = tid; i < NHID; i += TBB) {
            const unsigned u = keys[i];
            if ((u >> 16) == thr16) {
                const unsigned p = atomicAdd(&candCnt, 1u);
                if (p < MAXCAND) { candKey[p] = u; candIdx[p] = i; }
            }
        }
        __syncthreads();
        const int L = (candCnt < MAXCAND) ? (int)candCnt : MAXCAND;

        // resolve: rank candidates by (key desc, index asc); top-k2 win
        if (tid < L) {
            const unsigned ku = candKey[tid];
            const int ii = candIdx[tid];
            int rank = 0;
            for (int j = 0; j < L; j++) {
                const unsigned kj = candKey[j];
                rank += (kj > ku) || (kj == ku && candIdx[j] < ii);
            }
            if (rank < k2) {
                const unsigned p = atomicAdd(&winCnt, 1u);
                winList[p] = ii;
            }
        }
        __syncthreads();
        const int Wn = (int)winCnt;

        // phase 4: accumulate logits over winners (deterministic strided partials)
        float acc[NCLS];
        #pragma unroll
        for (int c = 0; c < NCLS; c++) acc[c] = 0.f;

        for (int i = tid; i < NHID; i += TBB) {
            const unsigned t16 = keys[i] >> 16;
            bool win = (t16 > thr16);
            if (!win && t16 == thr16) {
                for (int w = 0; w < Wn; w++) win |= (winList[w] == i);
            }
            if (win) {
                const float hv = hs[i];
                #pragma unroll
                for (int c = 0; c < NCLS; c++)
                    acc[c] = fmaf(hv, __ldg(&W2[c * NHID + i]), acc[c]);
            }
        }

        #pragma unroll
        for (int off = 16; off; off >>= 1)
            #pragma unroll
            for (int c = 0; c < NCLS; c++)
                acc[c] += __shfl_xor_sync(0xFFFFFFFFu, acc[c], off);
        if (lane == 0)
            #pragma unroll
            for (int c = 0; c < NCLS; c++) red[warp * NCLS + c] = acc[c];
        __syncthreads();

        if (tid == 0) {
            float lg[NCLS];
            #pragma unroll
            for (int c = 0; c < NCLS; c++) {
                float s = b2[c];
                #pragma unroll
                for (int w = 0; w < 8; w++) s += red[w * NCLS + c];
                lg[c] = s;
            }
            float mx = lg[0];
            #pragma unroll
            for (int c = 1; c < NCLS; c++) mx = fmaxf(mx, lg[c]);
            float se = 0.f;
            #pragma unroll
            for (int c = 0; c < NCLS; c++) se += expf(lg[c] - mx);
            const float lse = mx + logf(se);
            float* orow = out + (size_t)row * NCLS;
            #pragma unroll
            for (int c = 0; c < NCLS; c++) orow[c] = lg[c] - lse;
        }
        __syncthreads();
    }
}

// ---------------- launch ----------------
extern "C" void kernel_launch(void* const* d_in, const int* in_sizes, int n_in,
                              void* d_out, int out_size)
{
    const float* x    = (const float*)d_in[0];   // [16384, 784]
    const float* W1   = (const float*)d_in[1];   // [2000, 784]
    const float* b1   = (const float*)d_in[2];   // [2000]
    const float* W2   = (const float*)d_in[3];   // [10, 2000]
    const float* b2   = (const float*)d_in[4];   // [10]
    const float* duty = (const float*)d_in[5];   // [2000]
    float* out = (float*)d_out;                  // [16384, 10]

    float*  h;    cudaGetSymbolAddress((void**)&h,   g_h);
    __half* xhi;  cudaGetSymbolAddress((void**)&xhi, g_xhi);
    __half* xlo;  cudaGetSymbolAddress((void**)&xlo, g_xlo);
    __half* whi;  cudaGetSymbolAddress((void**)&whi, g_whi);
    __half* wlo;  cudaGetSymbolAddress((void**)&wlo, g_wlo);

    split_kernel<<<1024, 256>>>(x,  xhi, xlo, (BATCH * IN_DIM) / 4);
    split_kernel<<<512,  256>>>(W1, whi, wlo, (NHID  * IN_DIM) / 4);

    cudaFuncSetAttribute(gemm1_mma, cudaFuncAttributeMaxDynamicSharedMemorySize, SMEM_GEMM);
    dim3 gridG((NHID + BN - 1) / BN, BATCH / BM);   // (16, 128)
    gemm1_mma<<<gridG, 256, SMEM_GEMM>>>(xhi, xlo, whi, wlo, b1, h);

    kwin_head_kernel<<<BATCH / ROWS_B, TBB>>>(h, W2, b2, duty, out);
}